// round 9
// baseline (speedup 1.0000x reference)
#include <cuda_runtime.h>
#include <math.h>

#define NND    2048      // nodes
#define HID    640       // LSTM hidden
#define LEN_IN 8500
#define G4H    2560      // 4*HID
#define NEDGE  65536
#define SCAN_G 80        // persistent CTAs for scan
#define DPC    8         // dims per CTA (640/80)
#define RPC    32        // w_hh rows per CTA (4*DPC)
#define SCAN_SMEM ((RPC * HID + HID) * 4)   // 84480 bytes

// ---------------- device scratch (static, no runtime alloc) ----------------
__device__ float d_xp [NND * G4H];
__device__ float d_hsA[NND * HID];
__device__ float d_hsB[NND * HID];
__device__ float d_hbuf[2 * HID];
__device__ float d_Amat[(size_t)NND * NND];
__device__ float d_xw [NND * 320];
__device__ float d_gout[NND * 320];
__device__ float d_deg [NND];
__device__ float d_dinv[NND];
__device__ unsigned d_arr[SCAN_G * 32];      // arrival flags, one 128B line per CTA

#define BUF_XP   0
#define BUF_HSA  1
#define BUF_HSB  2
#define BUF_AMAT 3
#define BUF_XW   4
#define BUF_GOUT 5
__device__ __forceinline__ float* bufptr(int id, const float* ext) {
    switch (id) {
        case BUF_XP:   return d_xp;
        case BUF_HSA:  return d_hsA;
        case BUF_HSB:  return d_hsB;
        case BUF_AMAT: return d_Amat;
        case BUF_XW:   return d_xw;
        case BUF_GOUT: return d_gout;
        default:       return (float*)ext;
    }
}

__device__ __forceinline__ float sigm(float x) { return 1.f / (1.f + expf(-x)); }

// ---------------- SGEMM: 128x128 tile, BK=16, 2-stage SMEM ping-pong ----------------
// BT=true : B is [N,K] row-major  (C = A @ B^T);  BT=false: B is [K,N] row-major
template<bool BT>
__global__ __launch_bounds__(256) void gemm_kernel(
    const float* __restrict__ Aext, int Aid,
    const float* __restrict__ Bext, int Bid,
    const float* __restrict__ bias0, const float* __restrict__ bias1,
    int Cid, int M, int N, int K)
{
    const float* A = bufptr(Aid, Aext);
    const float* B = bufptr(Bid, Bext);
    float*       C = bufptr(Cid, nullptr);

    __shared__ __align__(16) float As[2][16][128];
    __shared__ __align__(16) float Bs[2][16][128];
    const int tid = threadIdx.x;
    const int bm = blockIdx.y * 128, bn = blockIdx.x * 128;
    const int tx = tid & 15, ty = tid >> 4;

    // load coords: A and B(BT) tiles are 128 rows x 16 k-cols; B(KN) is 16 x 128
    const int ar  = tid >> 1, ac0 = (tid & 1) * 8;
    const int bkk = tid >> 4, bnc0 = (tid & 15) * 8;

    float acc[8][8];
#pragma unroll
    for (int i = 0; i < 8; i++)
#pragma unroll
        for (int j = 0; j < 8; j++) acc[i][j] = 0.f;

    const int nT = (K + 15) / 16;

    // tile 0 -> smem[0]
    {
        int m = bm + ar;
#pragma unroll
        for (int i = 0; i < 8; i++) {
            int k = ac0 + i;
            As[0][ac0 + i][ar] = (m < M && k < K) ? A[(size_t)m * K + k] : 0.f;
        }
        if (BT) {
            int n = bn + ar;
#pragma unroll
            for (int i = 0; i < 8; i++) {
                int k = ac0 + i;
                Bs[0][ac0 + i][ar] = (n < N && k < K) ? B[(size_t)n * K + k] : 0.f;
            }
        } else {
#pragma unroll
            for (int i = 0; i < 8; i++) {
                int n = bn + bnc0 + i;
                Bs[0][bkk][bnc0 + i] = (bkk < K && n < N) ? B[(size_t)bkk * N + n] : 0.f;
            }
        }
    }
    __syncthreads();

    float ra[8], rb[8];
    for (int tI = 0; tI < nT; tI++) {
        const int s = tI & 1;
        const bool more = (tI + 1 < nT);
        const int k0n = (tI + 1) * 16;
        if (more) {   // prefetch next tile into registers
            int m = bm + ar;
#pragma unroll
            for (int i = 0; i < 8; i++) {
                int k = k0n + ac0 + i;
                ra[i] = (m < M && k < K) ? A[(size_t)m * K + k] : 0.f;
            }
            if (BT) {
                int n = bn + ar;
#pragma unroll
                for (int i = 0; i < 8; i++) {
                    int k = k0n + ac0 + i;
                    rb[i] = (n < N && k < K) ? B[(size_t)n * K + k] : 0.f;
                }
            } else {
                int k = k0n + bkk;
#pragma unroll
                for (int i = 0; i < 8; i++) {
                    int n = bn + bnc0 + i;
                    rb[i] = (k < K && n < N) ? B[(size_t)k * N + n] : 0.f;
                }
            }
        }

#pragma unroll
        for (int kk = 0; kk < 16; kk++) {
            float a[8], b[8];
            *(float4*)&a[0] = *(const float4*)&As[s][kk][ty * 8];
            *(float4*)&a[4] = *(const float4*)&As[s][kk][ty * 8 + 4];
            *(float4*)&b[0] = *(const float4*)&Bs[s][kk][tx * 8];
            *(float4*)&b[4] = *(const float4*)&Bs[s][kk][tx * 8 + 4];
#pragma unroll
            for (int i = 0; i < 8; i++)
#pragma unroll
                for (int j = 0; j < 8; j++) acc[i][j] += a[i] * b[j];
        }

        if (more) {   // commit prefetched tile to the other stage
#pragma unroll
            for (int i = 0; i < 8; i++) As[s ^ 1][ac0 + i][ar] = ra[i];
            if (BT) {
#pragma unroll
                for (int i = 0; i < 8; i++) Bs[s ^ 1][ac0 + i][ar] = rb[i];
            } else {
#pragma unroll
                for (int i = 0; i < 8; i++) Bs[s ^ 1][bkk][bnc0 + i] = rb[i];
            }
            __syncthreads();
        }
    }
#pragma unroll
    for (int i = 0; i < 8; i++) {
        int m = bm + ty * 8 + i;
        if (m >= M) continue;
#pragma unroll
        for (int j = 0; j < 8; j++) {
            int n = bn + tx * 8 + j;
            if (n >= N) continue;
            float v = acc[i][j];
            if (bias0) v += bias0[n];
            if (bias1) v += bias1[n];
            C[(size_t)m * N + n] = v;
        }
    }
}

// ---------------- persistent LSTM scan: 80 CTAs x 512 thr, 8 dims/CTA ----------------
// 32 w_hh rows resident in 84KB dynamic SMEM; one CTA per SM (grid<=148, wave-1 placement).
__global__ __launch_bounds__(512) void lstm_scan_kernel(
    const float* __restrict__ w_hh,  // [2560, 640]
    int hs_id)                       // output buffer id ([2048, 640])
{
    extern __shared__ float sm[];
    float* Ws  = sm;                 // [RPC][HID]
    float* h_s = sm + RPC * HID;     // [HID]
    __shared__ float gate_s[RPC];
    __shared__ float xg_s[RPC];
    __shared__ float c_s[DPC];

    const float* xp = d_xp;
    float* hs_out = bufptr(hs_id, nullptr);
    const int tid = threadIdx.x;
    const int lane = tid & 31, wrp = tid >> 5;   // 16 warps
    const int j0 = blockIdx.x * DPC;

    // preload 32 recurrent rows: r = 4*d+g -> w_hh row g*HID + (j0+d)
    for (int r = 0; r < RPC; r++) {
        const float* src = w_hh + (size_t)((r & 3) * HID + j0 + (r >> 2)) * HID;
        for (int k = tid; k < HID; k += 512) Ws[r * HID + k] = src[k];
    }
    if (tid < DPC) c_s[tid] = 0.f;
    __syncthreads();

    for (int t = 0; t < NND; t++) {
        if (t == 0) { for (int k = tid; k < HID; k += 512) h_s[k] = 0.f; }
        else {
            const float* hp = d_hbuf + ((t - 1) & 1) * HID;
            for (int k = tid; k < HID; k += 512) h_s[k] = hp[k];
        }
        if (tid < RPC)
            xg_s[tid] = xp[(size_t)t * G4H + (tid & 3) * HID + j0 + (tid >> 2)];
        __syncthreads();

        // two gate rows per warp
#pragma unroll
        for (int rr = 0; rr < 2; rr++) {
            const int r = wrp * 2 + rr;
            const float* wr = Ws + r * HID;
            float s = 0.f;
#pragma unroll
            for (int i = 0; i < 20; i++) s += h_s[lane + 32 * i] * wr[lane + 32 * i];
#pragma unroll
            for (int o = 16; o; o >>= 1) s += __shfl_xor_sync(0xffffffffu, s, o);
            if (lane == 0) gate_s[r] = s;
        }
        __syncthreads();

        if (tid < DPC) {
            const int d = tid, j = j0 + d;
            float ig = gate_s[d * 4 + 0] + xg_s[d * 4 + 0];
            float fg = gate_s[d * 4 + 1] + xg_s[d * 4 + 1];
            float gg = gate_s[d * 4 + 2] + xg_s[d * 4 + 2];
            float og = gate_s[d * 4 + 3] + xg_s[d * 4 + 3];
            float c = sigm(fg) * c_s[d] + sigm(ig) * tanhf(gg);
            c_s[d] = c;
            float h = sigm(og) * tanhf(c);
            d_hbuf[(t & 1) * HID + j] = h;
            hs_out[(size_t)t * HID + j] = h;
        }
        __syncthreads();

        // ---- flag-array grid barrier over 80 CTAs ----
        const unsigned epoch = (unsigned)(t + 1);
        if (tid == 0) {
            __threadfence();
            *(volatile unsigned*)&d_arr[blockIdx.x * 32] = epoch;
        }
        if (wrp == 0) {
            bool ok;
            do {
                unsigned v0 = *(volatile unsigned*)&d_arr[lane * 32];
                unsigned v1 = *(volatile unsigned*)&d_arr[(lane + 32) * 32];
                unsigned v2 = (lane < 16) ? *(volatile unsigned*)&d_arr[(lane + 64) * 32] : epoch;
                ok = (v0 >= epoch) && (v1 >= epoch) && (v2 >= epoch);
            } while (!__all_sync(0xffffffffu, ok));
            if (lane == 0) __threadfence();
        }
        __syncthreads();
    }
}

// ---------------- graph-construction kernels (edge_index is INT32 [2, E]) ----------------
__global__ void zeroA_kernel() {
    size_t i = (size_t)blockIdx.x * blockDim.x + threadIdx.x;
    size_t total = (size_t)NND * NND;
    size_t stride = (size_t)gridDim.x * blockDim.x;
    for (; i < total; i += stride) d_Amat[i] = 0.f;
}
__global__ void deg_init_kernel() {
    int i = blockIdx.x * blockDim.x + threadIdx.x;
    if (i < NND) d_deg[i] = 1.f;
}
__global__ void deg_accum_kernel(const int* __restrict__ ei) {
    int e = blockIdx.x * blockDim.x + threadIdx.x;
    if (e < NEDGE) {
        int dn = ei[NEDGE + e] & (NND - 1);
        atomicAdd(&d_deg[dn], 1.f);
    }
}
__global__ void dinv_kernel() {
    int i = blockIdx.x * blockDim.x + threadIdx.x;
    if (i < NND) d_dinv[i] = rsqrtf(d_deg[i]);
}
__global__ void afill_kernel(const int* __restrict__ ei) {
    int i = blockIdx.x * blockDim.x + threadIdx.x;
    if (i < NEDGE) {
        int s = ei[i] & (NND - 1);
        int dn = ei[NEDGE + i] & (NND - 1);
        atomicAdd(&d_Amat[(size_t)dn * NND + s], d_dinv[s] * d_dinv[dn]);
    } else if (i < NEDGE + NND) {
        int n = i - NEDGE;
        float v = d_dinv[n];
        atomicAdd(&d_Amat[(size_t)n * NND + n], v * v);
    }
}
__global__ void bar_reset_kernel() {
    int i = blockIdx.x * blockDim.x + threadIdx.x;
    if (i < SCAN_G * 32) d_arr[i] = 0u;
}

// ---------------- fused LeakyReLU + BatchNorm per column ----------------
__global__ __launch_bounds__(256) void bn_lrelu_kernel(int out_id, int C)
{
    const float* in = d_gout;
    float* out = bufptr(out_id, nullptr);
    __shared__ float buf[NND];
    __shared__ float red[256];
    const int c = blockIdx.x, tid = threadIdx.x;
    float s = 0.f;
    for (int r = tid; r < NND; r += 256) {
        float v = in[(size_t)r * C + c];
        v = v >= 0.f ? v : 0.01f * v;
        buf[r] = v; s += v;
    }
    red[tid] = s; __syncthreads();
    for (int o = 128; o; o >>= 1) { if (tid < o) red[tid] += red[tid + o]; __syncthreads(); }
    const float mean = red[0] * (1.f / NND);
    __syncthreads();
    float s2 = 0.f;
    for (int r = tid; r < NND; r += 256) { float d = buf[r] - mean; s2 += d * d; }
    red[tid] = s2; __syncthreads();
    for (int o = 128; o; o >>= 1) { if (tid < o) red[tid] += red[tid + o]; __syncthreads(); }
    const float scale = rsqrtf(red[0] * (1.f / NND) + 1e-5f);
    for (int r = tid; r < NND; r += 256)
        out[(size_t)r * C + c] = (buf[r] - mean) * scale;
}

// ---------------- global_add_pool + 3-layer FC head ----------------
__global__ __launch_bounds__(1024) void pool_fc_kernel(
    int x_id,
    const float* __restrict__ fw1, const float* __restrict__ fb1,
    const float* __restrict__ fw2, const float* __restrict__ fb2,
    const float* __restrict__ fw3, const float* __restrict__ fb3,
    float* __restrict__ out)       // [16] y ++ [800] emb
{
    const float* x = bufptr(x_id, nullptr);
    __shared__ float emb[16 * 50], h1[16 * 32], h2[16 * 16];
    const int tid = threadIdx.x;
    if (tid < 800) {
        int b = tid / 50, f = tid % 50;
        float s = 0.f;
        for (int r = 0; r < 128; r++) s += x[(size_t)(b * 128 + r) * 50 + f];
        emb[b * 50 + f] = s;
        out[16 + b * 50 + f] = s;
    }
    __syncthreads();
    if (tid < 512) {
        int b = tid / 32, o = tid % 32;
        float s = fb1[o];
        for (int f = 0; f < 50; f++) s += emb[b * 50 + f] * fw1[f * 32 + o];
        h1[b * 32 + o] = s;
    }
    __syncthreads();
    if (tid < 256) {
        int b = tid / 16, o = tid % 16;
        float s = fb2[o];
        for (int f = 0; f < 32; f++) s += h1[b * 32 + f] * fw2[f * 16 + o];
        h2[b * 16 + o] = s;
    }
    __syncthreads();
    if (tid < 16) {
        float s = fb3[0];
        for (int f = 0; f < 16; f++) s += h2[tid * 16 + f] * fw3[f];
        out[tid] = s;
    }
}

// ---------------- driver (kernel launches ONLY) ----------------
static inline dim3 gemm_grid(int M, int N) { return dim3((N + 127) / 128, (M + 127) / 128); }

extern "C" void kernel_launch(void* const* d_in, const int* in_sizes, int n_in,
                              void* d_out, int out_size)
{
    const float* x_in = (const float*)d_in[0];
    const int*   ei   = (const int*)d_in[1];          // int32 [2, 65536]
    const float* w_ih[3] = {(const float*)d_in[2], (const float*)d_in[6],  (const float*)d_in[10]};
    const float* w_hh[3] = {(const float*)d_in[3], (const float*)d_in[7],  (const float*)d_in[11]};
    const float* b_ih[3] = {(const float*)d_in[4], (const float*)d_in[8],  (const float*)d_in[12]};
    const float* b_hh[3] = {(const float*)d_in[5], (const float*)d_in[9],  (const float*)d_in[13]};
    const float* gw[4] = {(const float*)d_in[14], (const float*)d_in[16], (const float*)d_in[18], (const float*)d_in[20]};
    const float* gb[4] = {(const float*)d_in[15], (const float*)d_in[17], (const float*)d_in[19], (const float*)d_in[21]};
    const float* fw1 = (const float*)d_in[22]; const float* fb1 = (const float*)d_in[23];
    const float* fw2 = (const float*)d_in[24]; const float* fb2 = (const float*)d_in[25];
    const float* fw3 = (const float*)d_in[26]; const float* fb3 = (const float*)d_in[27];
    float* out = (float*)d_out;

    // allow 84KB dynamic SMEM for the scan kernel (idempotent attribute set)
    static int smem_set = 0;
    if (!smem_set) {
        cudaFuncSetAttribute(lstm_scan_kernel,
                             cudaFuncAttributeMaxDynamicSharedMemorySize, SCAN_SMEM);
        smem_set = 1;
    }

    // ---- LSTM layer 0 ----
    gemm_kernel<true><<<gemm_grid(NND, G4H), 256>>>(x_in, -1, w_ih[0], -1, b_ih[0], b_hh[0], BUF_XP, NND, G4H, LEN_IN);
    bar_reset_kernel<<<(SCAN_G * 32 + 255) / 256, 256>>>();
    lstm_scan_kernel<<<SCAN_G, 512, SCAN_SMEM>>>(w_hh[0], BUF_HSA);
    // ---- LSTM layer 1 ----
    gemm_kernel<true><<<gemm_grid(NND, G4H), 256>>>(nullptr, BUF_HSA, w_ih[1], -1, b_ih[1], b_hh[1], BUF_XP, NND, G4H, HID);
    bar_reset_kernel<<<(SCAN_G * 32 + 255) / 256, 256>>>();
    lstm_scan_kernel<<<SCAN_G, 512, SCAN_SMEM>>>(w_hh[1], BUF_HSB);
    // ---- LSTM layer 2 ----
    gemm_kernel<true><<<gemm_grid(NND, G4H), 256>>>(nullptr, BUF_HSB, w_ih[2], -1, b_ih[2], b_hh[2], BUF_XP, NND, G4H, HID);
    bar_reset_kernel<<<(SCAN_G * 32 + 255) / 256, 256>>>();
    lstm_scan_kernel<<<SCAN_G, 512, SCAN_SMEM>>>(w_hh[2], BUF_HSA);

    // ---- build dense normalized adjacency A ----
    zeroA_kernel<<<1024, 256>>>();
    deg_init_kernel<<<(NND + 255) / 256, 256>>>();
    deg_accum_kernel<<<(NEDGE + 255) / 256, 256>>>(ei);
    dinv_kernel<<<(NND + 255) / 256, 256>>>();
    afill_kernel<<<(NEDGE + NND + 255) / 256, 256>>>(ei);

    // ---- GCN layers ----
    const int dims[5] = {HID, 320, 180, 90, 50};
    int cur = BUF_HSA, nxt = BUF_HSB;
    for (int l = 0; l < 4; l++) {
        const int di = dims[l], dn = dims[l + 1];
        gemm_kernel<false><<<gemm_grid(NND, dn), 256>>>(nullptr, cur, gw[l], -1, nullptr, nullptr, BUF_XW, NND, dn, di);
        gemm_kernel<false><<<gemm_grid(NND, dn), 256>>>(nullptr, BUF_AMAT, nullptr, BUF_XW, gb[l], nullptr, BUF_GOUT, NND, dn, NND);
        bn_lrelu_kernel<<<dn, 256>>>(nxt, dn);
        int t = cur; cur = nxt; nxt = t;
    }

    // ---- pool + FC head ----
    pool_fc_kernel<<<1, 1024>>>(cur, fw1, fb1, fw2, fb2, fw3, fb3, out);
}

// round 10
// speedup vs baseline: 1.3273x; 1.3273x over previous
#include <cuda_runtime.h>
#include <math.h>

#define NND    2048      // nodes
#define HID    640       // LSTM hidden
#define LEN_IN 8500
#define G4H    2560      // 4*HID
#define NEDGE  65536
#define LSTM_G 160       // persistent CTAs for scan (640/160 = 4 dims each)

// ---------------- device scratch (static, no runtime alloc) ----------------
__device__ float d_xp [NND * G4H];           // 21 MB  gate pre-activations
__device__ float d_hsA[NND * HID];
__device__ float d_hsB[NND * HID];
__device__ float d_hbuf[2 * HID];            // ping-pong h state
__device__ float d_Amat[(size_t)NND * NND];  // dense normalized adjacency
__device__ float d_xw [NND * 320];
__device__ float d_gout[NND * 320];
__device__ float d_deg [NND];
__device__ float d_dinv[NND];
__device__ unsigned d_bar;

#define BUF_XP   0
#define BUF_HSA  1
#define BUF_HSB  2
#define BUF_AMAT 3
#define BUF_XW   4
#define BUF_GOUT 5
__device__ __forceinline__ float* bufptr(int id, const float* ext) {
    switch (id) {
        case BUF_XP:   return d_xp;
        case BUF_HSA:  return d_hsA;
        case BUF_HSB:  return d_hsB;
        case BUF_AMAT: return d_Amat;
        case BUF_XW:   return d_xw;
        case BUF_GOUT: return d_gout;
        default:       return (float*)ext;
    }
}

__device__ __forceinline__ float sigm(float x) { return 1.f / (1.f + expf(-x)); }

// ---------------- SGEMM: 128x128 tile, BK=16, 2-stage ping-pong, 2 CTAs/SM ----------------
// BT=true : B is [N,K] row-major  (C = A @ B^T);  BT=false: B is [K,N] row-major
template<bool BT>
__global__ __launch_bounds__(256, 2) void gemm_kernel(
    const float* __restrict__ Aext, int Aid,
    const float* __restrict__ Bext, int Bid,
    const float* __restrict__ bias0, const float* __restrict__ bias1,
    int Cid, int M, int N, int K)
{
    const float* A = bufptr(Aid, Aext);
    const float* B = bufptr(Bid, Bext);
    float*       C = bufptr(Cid, nullptr);

    __shared__ __align__(16) float As[2][16][128];
    __shared__ __align__(16) float Bs[2][16][128];
    const int tid = threadIdx.x;
    const int bm = blockIdx.y * 128, bn = blockIdx.x * 128;
    const int tx = tid & 15, ty = tid >> 4;

    const int ar  = tid >> 1, ac0 = (tid & 1) * 8;    // 128 rows x 16 k-cols loads
    const int bkk = tid >> 4, bnc0 = (tid & 15) * 8;  // 16 x 128 loads (KN layout)

    float acc[8][8];
#pragma unroll
    for (int i = 0; i < 8; i++)
#pragma unroll
        for (int j = 0; j < 8; j++) acc[i][j] = 0.f;

    const int nT = (K + 15) / 16;

    {   // tile 0 -> stage 0
        int m = bm + ar;
#pragma unroll
        for (int i = 0; i < 8; i++) {
            int k = ac0 + i;
            As[0][ac0 + i][ar] = (m < M && k < K) ? A[(size_t)m * K + k] : 0.f;
        }
        if (BT) {
            int n = bn + ar;
#pragma unroll
            for (int i = 0; i < 8; i++) {
                int k = ac0 + i;
                Bs[0][ac0 + i][ar] = (n < N && k < K) ? B[(size_t)n * K + k] : 0.f;
            }
        } else {
#pragma unroll
            for (int i = 0; i < 8; i++) {
                int n = bn + bnc0 + i;
                Bs[0][bkk][bnc0 + i] = (bkk < K && n < N) ? B[(size_t)bkk * N + n] : 0.f;
            }
        }
    }
    __syncthreads();

    float ra[8], rb[8];
    for (int tI = 0; tI < nT; tI++) {
        const int s = tI & 1;
        const bool more = (tI + 1 < nT);
        const int k0n = (tI + 1) * 16;
        if (more) {   // prefetch next tile into registers
            int m = bm + ar;
#pragma unroll
            for (int i = 0; i < 8; i++) {
                int k = k0n + ac0 + i;
                ra[i] = (m < M && k < K) ? A[(size_t)m * K + k] : 0.f;
            }
            if (BT) {
                int n = bn + ar;
#pragma unroll
                for (int i = 0; i < 8; i++) {
                    int k = k0n + ac0 + i;
                    rb[i] = (n < N && k < K) ? B[(size_t)n * K + k] : 0.f;
                }
            } else {
                int k = k0n + bkk;
#pragma unroll
                for (int i = 0; i < 8; i++) {
                    int n = bn + bnc0 + i;
                    rb[i] = (k < K && n < N) ? B[(size_t)k * N + n] : 0.f;
                }
            }
        }

#pragma unroll
        for (int kk = 0; kk < 16; kk++) {
            float a[8], b[8];
            *(float4*)&a[0] = *(const float4*)&As[s][kk][ty * 8];
            *(float4*)&a[4] = *(const float4*)&As[s][kk][ty * 8 + 4];
            *(float4*)&b[0] = *(const float4*)&Bs[s][kk][tx * 8];
            *(float4*)&b[4] = *(const float4*)&Bs[s][kk][tx * 8 + 4];
#pragma unroll
            for (int i = 0; i < 8; i++)
#pragma unroll
                for (int j = 0; j < 8; j++) acc[i][j] += a[i] * b[j];
        }

        if (more) {
#pragma unroll
            for (int i = 0; i < 8; i++) As[s ^ 1][ac0 + i][ar] = ra[i];
            if (BT) {
#pragma unroll
                for (int i = 0; i < 8; i++) Bs[s ^ 1][ac0 + i][ar] = rb[i];
            } else {
#pragma unroll
                for (int i = 0; i < 8; i++) Bs[s ^ 1][bkk][bnc0 + i] = rb[i];
            }
            __syncthreads();
        }
    }
#pragma unroll
    for (int i = 0; i < 8; i++) {
        int m = bm + ty * 8 + i;
        if (m >= M) continue;
#pragma unroll
        for (int j = 0; j < 8; j++) {
            int n = bn + tx * 8 + j;
            if (n >= N) continue;
            float v = acc[i][j];
            if (bias0) v += bias0[n];
            if (bias1) v += bias1[n];
            C[(size_t)m * N + n] = v;
        }
    }
}

// ---------------- persistent LSTM scan (R7 config: best measured) ----------------
// 160 CTAs x 512 threads; each CTA owns 4 hidden dims = 16 w_hh rows in SMEM,
// one warp per row. Grid barrier: atomic arrive + tight volatile spin.
__global__ __launch_bounds__(512) void lstm_scan_kernel(
    const float* __restrict__ w_hh,  // [2560, 640]
    int hs_id)                       // output buffer id ([2048, 640])
{
    const float* xp = d_xp;
    float* hs_out = bufptr(hs_id, nullptr);

    __shared__ float Ws[16][HID];    // 40 KB
    __shared__ float h_s[HID];
    __shared__ float gate_s[16];
    __shared__ float xg_s[16];
    __shared__ float c_s[4];
    const int tid = threadIdx.x;
    const int j0  = blockIdx.x * 4;
    const int lane = tid & 31, wrp = tid >> 5;   // 16 warps

    for (int r = 0; r < 16; r++) {
        const float* src = w_hh + (size_t)((r & 3) * HID + j0 + (r >> 2)) * HID;
        for (int k = tid; k < HID; k += 512) Ws[r][k] = src[k];
    }
    if (tid < 4) c_s[tid] = 0.f;
    __syncthreads();

    unsigned epoch = 0;
    for (int t = 0; t < NND; t++) {
        if (t == 0) { for (int k = tid; k < HID; k += 512) h_s[k] = 0.f; }
        else {
            const float* hp = d_hbuf + ((t - 1) & 1) * HID;
            for (int k = tid; k < HID; k += 512) h_s[k] = hp[k];
        }
        float xval = 0.f;
        if (tid < 16) xval = xp[(size_t)t * G4H + (tid & 3) * HID + j0 + (tid >> 2)];
        __syncthreads();

        {   // one warp per gate row
            const int r = wrp;
            float s = 0.f;
#pragma unroll
            for (int i = 0; i < 20; i++) s += h_s[lane + 32 * i] * Ws[r][lane + 32 * i];
#pragma unroll
            for (int o = 16; o; o >>= 1) s += __shfl_xor_sync(0xffffffffu, s, o);
            if (lane == 0) gate_s[r] = s;
        }
        if (tid < 16) xg_s[tid] = xval;
        __syncthreads();

        if (tid < 4) {
            const int d = tid, j = j0 + d;
            float ig = gate_s[d * 4 + 0] + xg_s[d * 4 + 0];
            float fg = gate_s[d * 4 + 1] + xg_s[d * 4 + 1];
            float gg = gate_s[d * 4 + 2] + xg_s[d * 4 + 2];
            float og = gate_s[d * 4 + 3] + xg_s[d * 4 + 3];
            float c = sigm(fg) * c_s[d] + sigm(ig) * tanhf(gg);
            c_s[d] = c;
            float h = sigm(og) * tanhf(c);
            d_hbuf[(t & 1) * HID + j] = h;
            hs_out[(size_t)t * HID + j] = h;
        }

        __syncthreads();
        epoch++;
        if (tid == 0) {
            __threadfence();
            atomicAdd(&d_bar, 1u);
            const unsigned target = epoch * LSTM_G;
            volatile unsigned* barp = &d_bar;
            while (*barp < target) { }
            __threadfence();
        }
        __syncthreads();
    }
}

// ---------------- graph-construction kernels (edge_index is INT32 [2, E]) ----------------
__global__ void zeroA_kernel() {
    size_t i = (size_t)blockIdx.x * blockDim.x + threadIdx.x;
    size_t total = (size_t)NND * NND;
    size_t stride = (size_t)gridDim.x * blockDim.x;
    for (; i < total; i += stride) d_Amat[i] = 0.f;
}
__global__ void deg_init_kernel() {
    int i = blockIdx.x * blockDim.x + threadIdx.x;
    if (i < NND) d_deg[i] = 1.f;
}
__global__ void deg_accum_kernel(const int* __restrict__ ei) {
    int e = blockIdx.x * blockDim.x + threadIdx.x;
    if (e < NEDGE) {
        int dn = ei[NEDGE + e] & (NND - 1);
        atomicAdd(&d_deg[dn], 1.f);
    }
}
__global__ void dinv_kernel() {
    int i = blockIdx.x * blockDim.x + threadIdx.x;
    if (i < NND) d_dinv[i] = rsqrtf(d_deg[i]);
}
__global__ void afill_kernel(const int* __restrict__ ei) {
    int i = blockIdx.x * blockDim.x + threadIdx.x;
    if (i < NEDGE) {
        int s = ei[i] & (NND - 1);
        int dn = ei[NEDGE + i] & (NND - 1);
        atomicAdd(&d_Amat[(size_t)dn * NND + s], d_dinv[s] * d_dinv[dn]);
    } else if (i < NEDGE + NND) {
        int n = i - NEDGE;
        float v = d_dinv[n];
        atomicAdd(&d_Amat[(size_t)n * NND + n], v * v);
    }
}
__global__ void bar_reset_kernel() { d_bar = 0u; }

// ---------------- fused LeakyReLU + BatchNorm per column ----------------
__global__ __launch_bounds__(256) void bn_lrelu_kernel(int out_id, int C)
{
    const float* in = d_gout;
    float* out = bufptr(out_id, nullptr);
    __shared__ float buf[NND];
    __shared__ float red[256];
    const int c = blockIdx.x, tid = threadIdx.x;
    float s = 0.f;
    for (int r = tid; r < NND; r += 256) {
        float v = in[(size_t)r * C + c];
        v = v >= 0.f ? v : 0.01f * v;
        buf[r] = v; s += v;
    }
    red[tid] = s; __syncthreads();
    for (int o = 128; o; o >>= 1) { if (tid < o) red[tid] += red[tid + o]; __syncthreads(); }
    const float mean = red[0] * (1.f / NND);
    __syncthreads();
    float s2 = 0.f;
    for (int r = tid; r < NND; r += 256) { float d = buf[r] - mean; s2 += d * d; }
    red[tid] = s2; __syncthreads();
    for (int o = 128; o; o >>= 1) { if (tid < o) red[tid] += red[tid + o]; __syncthreads(); }
    const float scale = rsqrtf(red[0] * (1.f / NND) + 1e-5f);
    for (int r = tid; r < NND; r += 256)
        out[(size_t)r * C + c] = (buf[r] - mean) * scale;
}

// ---------------- global_add_pool + 3-layer FC head ----------------
__global__ __launch_bounds__(1024) void pool_fc_kernel(
    int x_id,
    const float* __restrict__ fw1, const float* __restrict__ fb1,
    const float* __restrict__ fw2, const float* __restrict__ fb2,
    const float* __restrict__ fw3, const float* __restrict__ fb3,
    float* __restrict__ out)       // [16] y ++ [800] emb
{
    const float* x = bufptr(x_id, nullptr);
    __shared__ float emb[16 * 50], h1[16 * 32], h2[16 * 16];
    const int tid = threadIdx.x;
    if (tid < 800) {
        int b = tid / 50, f = tid % 50;
        float s = 0.f;
        for (int r = 0; r < 128; r++) s += x[(size_t)(b * 128 + r) * 50 + f];
        emb[b * 50 + f] = s;
        out[16 + b * 50 + f] = s;
    }
    __syncthreads();
    if (tid < 512) {
        int b = tid / 32, o = tid % 32;
        float s = fb1[o];
        for (int f = 0; f < 50; f++) s += emb[b * 50 + f] * fw1[f * 32 + o];
        h1[b * 32 + o] = s;
    }
    __syncthreads();
    if (tid < 256) {
        int b = tid / 16, o = tid % 16;
        float s = fb2[o];
        for (int f = 0; f < 32; f++) s += h1[b * 32 + f] * fw2[f * 16 + o];
        h2[b * 16 + o] = s;
    }
    __syncthreads();
    if (tid < 16) {
        float s = fb3[0];
        for (int f = 0; f < 16; f++) s += h2[tid * 16 + f] * fw3[f];
        out[tid] = s;
    }
}

// ---------------- driver (kernel launches ONLY) ----------------
static inline dim3 gemm_grid(int M, int N) { return dim3((N + 127) / 128, (M + 127) / 128); }

extern "C" void kernel_launch(void* const* d_in, const int* in_sizes, int n_in,
                              void* d_out, int out_size)
{
    const float* x_in = (const float*)d_in[0];
    const int*   ei   = (const int*)d_in[1];          // int32 [2, 65536]
    const float* w_ih[3] = {(const float*)d_in[2], (const float*)d_in[6],  (const float*)d_in[10]};
    const float* w_hh[3] = {(const float*)d_in[3], (const float*)d_in[7],  (const float*)d_in[11]};
    const float* b_ih[3] = {(const float*)d_in[4], (const float*)d_in[8],  (const float*)d_in[12]};
    const float* b_hh[3] = {(const float*)d_in[5], (const float*)d_in[9],  (const float*)d_in[13]};
    const float* gw[4] = {(const float*)d_in[14], (const float*)d_in[16], (const float*)d_in[18], (const float*)d_in[20]};
    const float* gb[4] = {(const float*)d_in[15], (const float*)d_in[17], (const float*)d_in[19], (const float*)d_in[21]};
    const float* fw1 = (const float*)d_in[22]; const float* fb1 = (const float*)d_in[23];
    const float* fw2 = (const float*)d_in[24]; const float* fb2 = (const float*)d_in[25];
    const float* fw3 = (const float*)d_in[26]; const float* fb3 = (const float*)d_in[27];
    float* out = (float*)d_out;

    // ---- LSTM layer 0 ----
    gemm_kernel<true><<<gemm_grid(NND, G4H), 256>>>(x_in, -1, w_ih[0], -1, b_ih[0], b_hh[0], BUF_XP, NND, G4H, LEN_IN);
    bar_reset_kernel<<<1, 1>>>();
    lstm_scan_kernel<<<LSTM_G, 512>>>(w_hh[0], BUF_HSA);
    // ---- LSTM layer 1 ----
    gemm_kernel<true><<<gemm_grid(NND, G4H), 256>>>(nullptr, BUF_HSA, w_ih[1], -1, b_ih[1], b_hh[1], BUF_XP, NND, G4H, HID);
    bar_reset_kernel<<<1, 1>>>();
    lstm_scan_kernel<<<LSTM_G, 512>>>(w_hh[1], BUF_HSB);
    // ---- LSTM layer 2 ----
    gemm_kernel<true><<<gemm_grid(NND, G4H), 256>>>(nullptr, BUF_HSB, w_ih[2], -1, b_ih[2], b_hh[2], BUF_XP, NND, G4H, HID);
    bar_reset_kernel<<<1, 1>>>();
    lstm_scan_kernel<<<LSTM_G, 512>>>(w_hh[2], BUF_HSA);

    // ---- build dense normalized adjacency A ----
    zeroA_kernel<<<1024, 256>>>();
    deg_init_kernel<<<(NND + 255) / 256, 256>>>();
    deg_accum_kernel<<<(NEDGE + 255) / 256, 256>>>(ei);
    dinv_kernel<<<(NND + 255) / 256, 256>>>();
    afill_kernel<<<(NEDGE + NND + 255) / 256, 256>>>(ei);

    // ---- GCN layers ----
    const int dims[5] = {HID, 320, 180, 90, 50};
    int cur = BUF_HSA, nxt = BUF_HSB;
    for (int l = 0; l < 4; l++) {
        const int di = dims[l], dn = dims[l + 1];
        gemm_kernel<false><<<gemm_grid(NND, dn), 256>>>(nullptr, cur, gw[l], -1, nullptr, nullptr, BUF_XW, NND, dn, di);
        gemm_kernel<false><<<gemm_grid(NND, dn), 256>>>(nullptr, BUF_AMAT, nullptr, BUF_XW, gb[l], nullptr, BUF_GOUT, NND, dn, NND);
        bn_lrelu_kernel<<<dn, 256>>>(nxt, dn);
        int t = cur; cur = nxt; nxt = t;
    }

    // ---- pool + FC head ----
    pool_fc_kernel<<<1, 1024>>>(cur, fw1, fb1, fw2, fb2, fw3, fb3, out);
}